// round 5
// baseline (speedup 1.0000x reference)
#include <cuda_runtime.h>
#include <cuda_bf16.h>
#include <math.h>

#define B_   8
#define L_   2048
#define DM_  512
#define H_   8
#define DH_  64
#define SK_  24
#define NTOP_ 24

// ---------------- device scratch (no cudaMalloc allowed) ----------------
__device__ float g_lnq [B_ * L_ * DM_];
__device__ float g_q   [B_ * L_ * DM_];
__device__ float g_k   [B_ * L_ * DM_];
__device__ float g_v   [B_ * L_ * DM_];
__device__ float g_out1[B_ * L_ * DM_];
__device__ float g_out2[B_ * L_ * DM_];
__device__ float g_M   [B_ * H_ * L_];
__device__ int   g_top [B_ * H_ * NTOP_];
__device__ int   g_sel [B_ * H_ * L_];
__device__ float g_upd [B_ * H_ * NTOP_ * DH_];
__device__ float g_padc[B_ * L_];

// ---------------- LayerNorm over last dim (512), one block per row ------
__global__ void ln_kernel(const float* __restrict__ x, const float* __restrict__ w,
                          const float* __restrict__ bb, float* __restrict__ out) {
    int row = blockIdx.x;
    int tid = threadIdx.x; // 256 threads, 2 elems each
    const float2* xr = reinterpret_cast<const float2*>(x + (size_t)row * DM_);
    float2 v = xr[tid];
    __shared__ float red[8];

    float s = v.x + v.y;
    #pragma unroll
    for (int o = 16; o; o >>= 1) s += __shfl_xor_sync(0xffffffffu, s, o);
    if ((tid & 31) == 0) red[tid >> 5] = s;
    __syncthreads();
    float tot = 0.f;
    #pragma unroll
    for (int i = 0; i < 8; i++) tot += red[i];
    float mean = tot * (1.f / DM_);

    float d0 = v.x - mean, d1 = v.y - mean;
    float sq = d0 * d0 + d1 * d1;
    __syncthreads();
    #pragma unroll
    for (int o = 16; o; o >>= 1) sq += __shfl_xor_sync(0xffffffffu, sq, o);
    if ((tid & 31) == 0) red[tid >> 5] = sq;
    __syncthreads();
    float vtot = 0.f;
    #pragma unroll
    for (int i = 0; i < 8; i++) vtot += red[i];
    float inv = rsqrtf(vtot * (1.f / DM_) + 1e-8f);

    float2 wv = reinterpret_cast<const float2*>(w)[tid];
    float2 bv = reinterpret_cast<const float2*>(bb)[tid];
    float2 o;
    o.x = wv.x * d0 * inv + bv.x;
    o.y = wv.y * d1 * inv + bv.y;
    reinterpret_cast<float2*>(out + (size_t)row * DM_)[tid] = o;
}

// ---------------- GEMM: C[M,512] = A[M,512] @ W[512,512] + bias ---------
// 128x128 tile, 256 threads, 8x8 per-thread microtile, K-tile 8
// smem row stride 132 floats (528B, 16B-aligned) so float4 LDS is legal.
__global__ void __launch_bounds__(256) gemm_bias(const float* __restrict__ A,
                                                 const float* __restrict__ W,
                                                 const float* __restrict__ bias,
                                                 float* __restrict__ C) {
    const int K = 512, N = 512;
    __shared__ float As[8][128 + 4];
    __shared__ float Bs[8][128 + 4];
    int tid = threadIdx.x;
    int bm = blockIdx.y * 128;
    int bn = blockIdx.x * 128;

    int arow = tid >> 1;
    int acol = (tid & 1) * 4;
    int brow = tid >> 5;
    int bcol = (tid & 31) * 4;
    int tx = tid & 15, ty = tid >> 4;

    float acc[8][8];
    #pragma unroll
    for (int i = 0; i < 8; i++)
        #pragma unroll
        for (int j = 0; j < 8; j++) acc[i][j] = 0.f;

    for (int k0 = 0; k0 < K; k0 += 8) {
        float4 av = *reinterpret_cast<const float4*>(&A[(size_t)(bm + arow) * K + k0 + acol]);
        As[acol + 0][arow] = av.x;
        As[acol + 1][arow] = av.y;
        As[acol + 2][arow] = av.z;
        As[acol + 3][arow] = av.w;
        float4 bv = *reinterpret_cast<const float4*>(&W[(size_t)(k0 + brow) * N + bn + bcol]);
        Bs[brow][bcol + 0] = bv.x;
        Bs[brow][bcol + 1] = bv.y;
        Bs[brow][bcol + 2] = bv.z;
        Bs[brow][bcol + 3] = bv.w;
        __syncthreads();
        #pragma unroll
        for (int kk = 0; kk < 8; kk++) {
            float4 a0 = *reinterpret_cast<const float4*>(&As[kk][ty * 8]);
            float4 a1 = *reinterpret_cast<const float4*>(&As[kk][ty * 8 + 4]);
            float4 b0 = *reinterpret_cast<const float4*>(&Bs[kk][tx * 8]);
            float4 b1 = *reinterpret_cast<const float4*>(&Bs[kk][tx * 8 + 4]);
            float a[8] = {a0.x, a0.y, a0.z, a0.w, a1.x, a1.y, a1.z, a1.w};
            float b[8] = {b0.x, b0.y, b0.z, b0.w, b1.x, b1.y, b1.z, b1.w};
            #pragma unroll
            for (int i = 0; i < 8; i++)
                #pragma unroll
                for (int j = 0; j < 8; j++) acc[i][j] += a[i] * b[j];
        }
        __syncthreads();
    }

    #pragma unroll
    for (int i = 0; i < 8; i++) {
        int row = bm + ty * 8 + i;
        #pragma unroll
        for (int j = 0; j < 8; j += 4) {
            int col = bn + tx * 8 + j;
            float4 o;
            o.x = acc[i][j + 0] + bias[col + 0];
            o.y = acc[i][j + 1] + bias[col + 1];
            o.z = acc[i][j + 2] + bias[col + 2];
            o.w = acc[i][j + 3] + bias[col + 3];
            *reinterpret_cast<float4*>(&C[(size_t)row * N + col]) = o;
        }
    }
}

// ---------------- sampled scores: M[b,h,i] = max_j(q.ks_j) - sum_j/L ----
// one block per (b,i): load 24 sampled k rows (full 512) + q row into smem,
// 8 warps each handle one head.
__global__ void sample_score_kernel(const float* __restrict__ q, const float* __restrict__ k,
                                    const int* __restrict__ idx, float* __restrict__ Mout) {
    int i = blockIdx.x, b = blockIdx.y;
    extern __shared__ float sh[];            // ks[24][512] then q[512]
    float* ks = sh;
    float* qs = sh + SK_ * DM_;
    __shared__ int sidx[SK_];
    int tid = threadIdx.x; // 256

    if (tid < SK_) sidx[tid] = idx[i * SK_ + tid];
    __syncthreads();

    const float4* qrow = reinterpret_cast<const float4*>(q + ((size_t)b * L_ + i) * DM_);
    for (int t = tid; t < DM_ / 4; t += 256)
        reinterpret_cast<float4*>(qs)[t] = qrow[t];
    for (int t = tid; t < SK_ * (DM_ / 4); t += 256) {
        int j = t >> 7, c = t & 127;
        reinterpret_cast<float4*>(ks + j * DM_)[c] =
            reinterpret_cast<const float4*>(k + ((size_t)b * L_ + sidx[j]) * DM_)[c];
    }
    __syncthreads();

    int w = tid >> 5, lane = tid & 31;
    int h = w;
    float mx = -INFINITY, sm = 0.f;
    #pragma unroll 4
    for (int j = 0; j < SK_; j++) {
        float p = qs[h * DH_ + lane]      * ks[j * DM_ + h * DH_ + lane]
                + qs[h * DH_ + 32 + lane] * ks[j * DM_ + h * DH_ + 32 + lane];
        #pragma unroll
        for (int o = 16; o; o >>= 1) p += __shfl_xor_sync(0xffffffffu, p, o);
        mx = fmaxf(mx, p);
        sm += p;
    }
    if (lane == 0)
        Mout[((size_t)(b * H_ + h)) * L_ + i] = mx - sm * (1.0f / (float)L_);
}

// ---------------- top-24 per (b,h), iterative argmax; also build sel map -
__global__ void topk_kernel(const float* __restrict__ M, int* __restrict__ top,
                            int* __restrict__ sel) {
    int bh = blockIdx.x;
    __shared__ float vals[L_];
    __shared__ float rv[256];
    __shared__ int   ri[256];
    int tid = threadIdx.x; // 256

    for (int t = tid; t < L_; t += 256) {
        vals[t] = M[(size_t)bh * L_ + t];
        sel[(size_t)bh * L_ + t] = 0;
    }
    __syncthreads();

    for (int u = 0; u < NTOP_; u++) {
        float best = -INFINITY; int bi = L_;
        for (int t = tid; t < L_; t += 256) {
            float v = vals[t];
            if (v > best) { best = v; bi = t; }
        }
        rv[tid] = best; ri[tid] = bi;
        __syncthreads();
        for (int s = 128; s > 0; s >>= 1) {
            if (tid < s) {
                float ov = rv[tid + s]; int oi = ri[tid + s];
                if (ov > rv[tid] || (ov == rv[tid] && oi < ri[tid])) {
                    rv[tid] = ov; ri[tid] = oi;
                }
            }
            __syncthreads();
        }
        int chosen = ri[0];
        if (tid == 0) {
            top[bh * NTOP_ + u] = chosen;
            sel[(size_t)bh * L_ + chosen] = u + 1;
            vals[chosen] = -INFINITY;
        }
        __syncthreads();
    }
}

// ---------------- full attention for each selected row ------------------
// grid (NTOP, B*H), 256 threads; scores over all 2048 keys kept in smem.
__global__ void attn_kernel(const float* __restrict__ q, const float* __restrict__ k,
                            const float* __restrict__ v, const float* __restrict__ pad,
                            const int* __restrict__ top, float* __restrict__ upd) {
    int u = blockIdx.x, bh = blockIdx.y;
    int b = bh >> 3, h = bh & 7;
    __shared__ float sc[L_];
    __shared__ float qs[DH_];
    __shared__ float red[8];
    __shared__ float bc[2];            // broadcast max, sum
    __shared__ float updp[4][DH_];
    int tid = threadIdx.x; // 256
    int w = tid >> 5, lane = tid & 31;

    int qi = top[bh * NTOP_ + u];
    float pd = pad[b * L_ + qi];
    if (tid < DH_) qs[tid] = q[((size_t)b * L_ + qi) * DM_ + h * DH_ + tid];
    __syncthreads();

    const float scale = 0.044194173824159216f; // 1/sqrt(512)
    for (int kk = tid; kk < L_; kk += 256) {
        const float4* kr = reinterpret_cast<const float4*>(
            &k[((size_t)b * L_ + kk) * DM_ + h * DH_]);
        float s0 = 0.f, s1 = 0.f, s2 = 0.f, s3 = 0.f;
        #pragma unroll
        for (int d = 0; d < DH_ / 4; d++) {
            float4 kv = kr[d];
            s0 += qs[d * 4 + 0] * kv.x;
            s1 += qs[d * 4 + 1] * kv.y;
            s2 += qs[d * 4 + 2] * kv.z;
            s3 += qs[d * 4 + 3] * kv.w;
        }
        float s = ((s0 + s1) + (s2 + s3)) * scale;
        bool m = (kk <= qi) && (pd != 0.f);
        sc[kk] = m ? s : -100000.0f;
    }
    __syncthreads();

    // block max
    float mx = -INFINITY;
    for (int kk = tid; kk < L_; kk += 256) mx = fmaxf(mx, sc[kk]);
    #pragma unroll
    for (int o = 16; o; o >>= 1) mx = fmaxf(mx, __shfl_xor_sync(0xffffffffu, mx, o));
    if (lane == 0) red[w] = mx;
    __syncthreads();
    if (tid == 0) {
        float m2 = red[0];
        #pragma unroll
        for (int i = 1; i < 8; i++) m2 = fmaxf(m2, red[i]);
        bc[0] = m2;
    }
    __syncthreads();
    float Mx = bc[0];

    // exponentiate + block sum
    float ls = 0.f;
    for (int kk = tid; kk < L_; kk += 256) {
        float e = __expf(sc[kk] - Mx);
        sc[kk] = e;
        ls += e;
    }
    #pragma unroll
    for (int o = 16; o; o >>= 1) ls += __shfl_xor_sync(0xffffffffu, ls, o);
    if (lane == 0) red[w] = ls;
    __syncthreads();
    if (tid == 0) {
        float s2 = 0.f;
        #pragma unroll
        for (int i = 0; i < 8; i++) s2 += red[i];
        bc[1] = s2;
    }
    __syncthreads();
    float invS = 1.0f / bc[1];

    // upd[d] = sum_k w_k * v[k,d]
    int d = tid & 63, g = tid >> 6;
    float acc = 0.f;
    for (int kk = g; kk < L_; kk += 4)
        acc += sc[kk] * v[((size_t)b * L_ + kk) * DM_ + h * DH_ + d];
    updp[g][d] = acc;
    __syncthreads();
    if (tid < DH_) {
        float r = (updp[0][tid] + updp[1][tid] + updp[2][tid] + updp[3][tid]) * invS;
        upd[((size_t)bh * NTOP_ + u) * DH_ + tid] = r;
    }
}

// ---------------- padding cumsum per batch -------------------------------
__global__ void padc_kernel(const float* __restrict__ pad, float* __restrict__ padc) {
    int b = blockIdx.x;
    if (threadIdx.x == 0) {
        float a = 0.f;
        for (int i = 0; i < L_; i++) {
            a += pad[b * L_ + i];
            padc[b * L_ + i] = a;
        }
    }
}

// ---------------- v_avg cumsum + scatter selected rows -------------------
// grid (H, B), 64 threads (one per dim)
__global__ void assemble_kernel(const float* __restrict__ v, const float* __restrict__ padc,
                                const int* __restrict__ sel, const float* __restrict__ upd,
                                float* __restrict__ out1) {
    int h = blockIdx.x, b = blockIdx.y;
    int d = threadIdx.x; // 64
    int bh = b * H_ + h;
    float acc = 0.f;
    for (int i = 0; i < L_; i++) {
        acc += v[((size_t)b * L_ + i) * DM_ + h * DH_ + d];
        int s = sel[(size_t)bh * L_ + i];
        float val;
        if (s > 0)
            val = upd[((size_t)bh * NTOP_ + (s - 1)) * DH_ + d];
        else
            val = acc / (padc[b * L_ + i] + 1e-12f);
        out1[((size_t)b * L_ + i) * DM_ + h * DH_ + d] = val;
    }
}

// ---------------- launch ------------------------------------------------
extern "C" void kernel_launch(void* const* d_in, const int* in_sizes, int n_in,
                              void* d_out, int out_size) {
    (void)in_sizes; (void)n_in; (void)out_size;
    const float* queries = (const float*)d_in[0];
    const float* keys    = (const float*)d_in[1];
    const float* values  = (const float*)d_in[2];
    const float* pad     = (const float*)d_in[3];
    const float* Wq      = (const float*)d_in[4];
    const float* bq      = (const float*)d_in[5];
    const float* Wk      = (const float*)d_in[6];
    const float* bk      = (const float*)d_in[7];
    const float* Wv      = (const float*)d_in[8];
    const float* bv      = (const float*)d_in[9];
    const float* Wf      = (const float*)d_in[10];
    const float* bf      = (const float*)d_in[11];
    const float* qln_w   = (const float*)d_in[12];
    const float* qln_b   = (const float*)d_in[13];
    const float* fln_w   = (const float*)d_in[14];
    const float* fln_b   = (const float*)d_in[15];
    const int*   idx     = (const int*)d_in[16];
    float* out = (float*)d_out;

    float *p_lnq, *p_q, *p_k, *p_v, *p_out1, *p_out2, *p_M, *p_upd, *p_padc;
    int *p_top, *p_sel;
    cudaGetSymbolAddress((void**)&p_lnq,  g_lnq);
    cudaGetSymbolAddress((void**)&p_q,    g_q);
    cudaGetSymbolAddress((void**)&p_k,    g_k);
    cudaGetSymbolAddress((void**)&p_v,    g_v);
    cudaGetSymbolAddress((void**)&p_out1, g_out1);
    cudaGetSymbolAddress((void**)&p_out2, g_out2);
    cudaGetSymbolAddress((void**)&p_M,    g_M);
    cudaGetSymbolAddress((void**)&p_upd,  g_upd);
    cudaGetSymbolAddress((void**)&p_padc, g_padc);
    cudaGetSymbolAddress((void**)&p_top,  g_top);
    cudaGetSymbolAddress((void**)&p_sel,  g_sel);

    const int smem_ss = (SK_ * DM_ + DM_) * sizeof(float); // 51200
    cudaFuncSetAttribute(sample_score_kernel,
                         cudaFuncAttributeMaxDynamicSharedMemorySize, smem_ss);

    int rowsBL = B_ * L_;

    // 1. LN on queries
    ln_kernel<<<rowsBL, 256>>>(queries, qln_w, qln_b, p_lnq);

    // 2. projections
    dim3 gg(DM_ / 128, rowsBL / 128);
    gemm_bias<<<gg, 256>>>(p_lnq, Wq, bq, p_q);
    gemm_bias<<<gg, 256>>>(keys,  Wk, bk, p_k);
    gemm_bias<<<gg, 256>>>(values, Wv, bv, p_v);

    // 3. sampled score statistic M
    dim3 gs(L_, B_);
    sample_score_kernel<<<gs, 256, smem_ss>>>(p_q, p_k, idx, p_M);

    // 4. top-24 per (b,h) + selection map
    topk_kernel<<<B_ * H_, 256>>>(p_M, p_top, p_sel);

    // 5. full attention on selected rows
    dim3 ga(NTOP_, B_ * H_);
    attn_kernel<<<ga, 256>>>(p_q, p_k, p_v, pad, p_top, p_upd);

    // 6. padding cumsum
    padc_kernel<<<B_, 32>>>(pad, p_padc);

    // 7. assemble v_avg + scatter
    dim3 gasm(H_, B_);
    assemble_kernel<<<gasm, 64>>>(p_v, p_padc, p_sel, p_upd, p_out1);

    // 8. output projection
    gemm_bias<<<gg, 256>>>(p_out1, Wf, bf, p_out2);

    // 9. final LN
    ln_kernel<<<rowsBL, 256>>>(p_out2, fln_w, fln_b, out);
}

// round 12
// speedup vs baseline: 1.7969x; 1.7969x over previous
#include <cuda_runtime.h>
#include <cuda_bf16.h>
#include <math.h>

#define B_   8
#define L_   2048
#define DM_  512
#define H_   8
#define DH_  64
#define SK_  24
#define NTOP_ 24

// ---------------- device scratch (no cudaMalloc allowed) ----------------
__device__ float g_lnq [B_ * L_ * DM_];
__device__ float g_q   [B_ * L_ * DM_];
__device__ float g_k   [B_ * L_ * DM_];
__device__ float g_v   [B_ * L_ * DM_];
__device__ float g_out1[B_ * L_ * DM_];
__device__ float g_out2[B_ * L_ * DM_];
__device__ float g_M   [B_ * H_ * L_];
__device__ int   g_top [B_ * H_ * NTOP_];
__device__ int   g_sel [B_ * H_ * L_];
__device__ float g_upd [B_ * H_ * NTOP_ * DH_];
__device__ float g_padc[B_ * L_];

// ---------------- LayerNorm over last dim (512), one block per row ------
__global__ void ln_kernel(const float* __restrict__ x, const float* __restrict__ w,
                          const float* __restrict__ bb, float* __restrict__ out) {
    int row = blockIdx.x;
    int tid = threadIdx.x; // 256 threads, 2 elems each
    const float2* xr = reinterpret_cast<const float2*>(x + (size_t)row * DM_);
    float2 v = xr[tid];
    __shared__ float red[8];

    float s = v.x + v.y;
    #pragma unroll
    for (int o = 16; o; o >>= 1) s += __shfl_xor_sync(0xffffffffu, s, o);
    if ((tid & 31) == 0) red[tid >> 5] = s;
    __syncthreads();
    float tot = 0.f;
    #pragma unroll
    for (int i = 0; i < 8; i++) tot += red[i];
    float mean = tot * (1.f / DM_);

    float d0 = v.x - mean, d1 = v.y - mean;
    float sq = d0 * d0 + d1 * d1;
    __syncthreads();
    #pragma unroll
    for (int o = 16; o; o >>= 1) sq += __shfl_xor_sync(0xffffffffu, sq, o);
    if ((tid & 31) == 0) red[tid >> 5] = sq;
    __syncthreads();
    float vtot = 0.f;
    #pragma unroll
    for (int i = 0; i < 8; i++) vtot += red[i];
    float inv = rsqrtf(vtot * (1.f / DM_) + 1e-8f);

    float2 wv = reinterpret_cast<const float2*>(w)[tid];
    float2 bv = reinterpret_cast<const float2*>(bb)[tid];
    float2 o;
    o.x = wv.x * d0 * inv + bv.x;
    o.y = wv.y * d1 * inv + bv.y;
    reinterpret_cast<float2*>(out + (size_t)row * DM_)[tid] = o;
}

// ---------------- GEMM body: C[M,512] = A[M,512] @ W[512,512] + bias ----
// 128x128 tile, 256 threads, 8x8 microtile, K-tile 8, software-pipelined
// global loads (prefetch next tile into regs during compute).
__device__ __forceinline__ void gemm_body(const float* __restrict__ A,
                                          const float* __restrict__ W,
                                          const float* __restrict__ bias,
                                          float* __restrict__ C,
                                          int bm, int bn) {
    const int K = 512, N = 512;
    __shared__ float As[8][128 + 4];
    __shared__ float Bs[8][128 + 4];
    int tid = threadIdx.x;

    int arow = tid >> 1;
    int acol = (tid & 1) * 4;
    int brow = tid >> 5;
    int bcol = (tid & 31) * 4;
    int tx = tid & 15, ty = tid >> 4;

    float acc[8][8];
    #pragma unroll
    for (int i = 0; i < 8; i++)
        #pragma unroll
        for (int j = 0; j < 8; j++) acc[i][j] = 0.f;

    // prologue: load tile 0 into regs
    float4 av = *reinterpret_cast<const float4*>(&A[(size_t)(bm + arow) * K + acol]);
    float4 bv = *reinterpret_cast<const float4*>(&W[(size_t)brow * N + bn + bcol]);

    for (int k0 = 0; k0 < K; k0 += 8) {
        // stage current tile to smem
        As[acol + 0][arow] = av.x;
        As[acol + 1][arow] = av.y;
        As[acol + 2][arow] = av.z;
        As[acol + 3][arow] = av.w;
        Bs[brow][bcol + 0] = bv.x;
        Bs[brow][bcol + 1] = bv.y;
        Bs[brow][bcol + 2] = bv.z;
        Bs[brow][bcol + 3] = bv.w;
        __syncthreads();

        // prefetch next tile (latency hidden under compute below)
        if (k0 + 8 < K) {
            av = *reinterpret_cast<const float4*>(&A[(size_t)(bm + arow) * K + k0 + 8 + acol]);
            bv = *reinterpret_cast<const float4*>(&W[(size_t)(k0 + 8 + brow) * N + bn + bcol]);
        }

        #pragma unroll
        for (int kk = 0; kk < 8; kk++) {
            float4 a0 = *reinterpret_cast<const float4*>(&As[kk][ty * 8]);
            float4 a1 = *reinterpret_cast<const float4*>(&As[kk][ty * 8 + 4]);
            float4 b0 = *reinterpret_cast<const float4*>(&Bs[kk][tx * 8]);
            float4 b1 = *reinterpret_cast<const float4*>(&Bs[kk][tx * 8 + 4]);
            float a[8] = {a0.x, a0.y, a0.z, a0.w, a1.x, a1.y, a1.z, a1.w};
            float b[8] = {b0.x, b0.y, b0.z, b0.w, b1.x, b1.y, b1.z, b1.w};
            #pragma unroll
            for (int i = 0; i < 8; i++)
                #pragma unroll
                for (int j = 0; j < 8; j++) acc[i][j] += a[i] * b[j];
        }
        __syncthreads();
    }

    #pragma unroll
    for (int i = 0; i < 8; i++) {
        int row = bm + ty * 8 + i;
        #pragma unroll
        for (int j = 0; j < 8; j += 4) {
            int col = bn + tx * 8 + j;
            float4 o;
            o.x = acc[i][j + 0] + bias[col + 0];
            o.y = acc[i][j + 1] + bias[col + 1];
            o.z = acc[i][j + 2] + bias[col + 2];
            o.w = acc[i][j + 3] + bias[col + 3];
            *reinterpret_cast<float4*>(&C[(size_t)row * N + col]) = o;
        }
    }
}

__global__ void __launch_bounds__(256, 2) gemm_bias(const float* __restrict__ A,
                                                    const float* __restrict__ W,
                                                    const float* __restrict__ bias,
                                                    float* __restrict__ C) {
    gemm_body(A, W, bias, C, blockIdx.y * 128, blockIdx.x * 128);
}

// fused q/k/v projection: blockIdx.z selects which GEMM
struct Gemm3Args {
    const float* A[3];
    const float* W[3];
    const float* bias[3];
    float* C[3];
};

__global__ void __launch_bounds__(256, 2) gemm_bias3(Gemm3Args args) {
    int z = blockIdx.z;
    gemm_body(args.A[z], args.W[z], args.bias[z], args.C[z],
              blockIdx.y * 128, blockIdx.x * 128);
}

// ---------------- sampled scores: M[b,h,i] = max_j(q.ks_j) - sum_j/L ----
__global__ void sample_score_kernel(const float* __restrict__ q, const float* __restrict__ k,
                                    const int* __restrict__ idx, float* __restrict__ Mout) {
    int i = blockIdx.x, b = blockIdx.y;
    extern __shared__ float sh[];            // ks[24][512] then q[512]
    float* ks = sh;
    float* qs = sh + SK_ * DM_;
    __shared__ int sidx[SK_];
    int tid = threadIdx.x; // 256

    if (tid < SK_) sidx[tid] = idx[i * SK_ + tid];
    __syncthreads();

    const float4* qrow = reinterpret_cast<const float4*>(q + ((size_t)b * L_ + i) * DM_);
    for (int t = tid; t < DM_ / 4; t += 256)
        reinterpret_cast<float4*>(qs)[t] = qrow[t];
    for (int t = tid; t < SK_ * (DM_ / 4); t += 256) {
        int j = t >> 7, c = t & 127;
        reinterpret_cast<float4*>(ks + j * DM_)[c] =
            reinterpret_cast<const float4*>(k + ((size_t)b * L_ + sidx[j]) * DM_)[c];
    }
    __syncthreads();

    int w = tid >> 5, lane = tid & 31;
    int h = w;
    float mx = -INFINITY, sm = 0.f;
    #pragma unroll 4
    for (int j = 0; j < SK_; j++) {
        float p = qs[h * DH_ + lane]      * ks[j * DM_ + h * DH_ + lane]
                + qs[h * DH_ + 32 + lane] * ks[j * DM_ + h * DH_ + 32 + lane];
        #pragma unroll
        for (int o = 16; o; o >>= 1) p += __shfl_xor_sync(0xffffffffu, p, o);
        mx = fmaxf(mx, p);
        sm += p;
    }
    if (lane == 0)
        Mout[((size_t)(b * H_ + h)) * L_ + i] = mx - sm * (1.0f / (float)L_);
}

// ---------------- top-24 per (b,h), iterative argmax; also build sel map -
__global__ void topk_kernel(const float* __restrict__ M, int* __restrict__ top,
                            int* __restrict__ sel) {
    int bh = blockIdx.x;
    __shared__ float vals[L_];
    __shared__ float rv[256];
    __shared__ int   ri[256];
    int tid = threadIdx.x; // 256

    for (int t = tid; t < L_; t += 256) {
        vals[t] = M[(size_t)bh * L_ + t];
        sel[(size_t)bh * L_ + t] = 0;
    }
    __syncthreads();

    for (int u = 0; u < NTOP_; u++) {
        float best = -INFINITY; int bi = L_;
        for (int t = tid; t < L_; t += 256) {
            float v = vals[t];
            if (v > best) { best = v; bi = t; }
        }
        rv[tid] = best; ri[tid] = bi;
        __syncthreads();
        for (int s = 128; s > 0; s >>= 1) {
            if (tid < s) {
                float ov = rv[tid + s]; int oi = ri[tid + s];
                if (ov > rv[tid] || (ov == rv[tid] && oi < ri[tid])) {
                    rv[tid] = ov; ri[tid] = oi;
                }
            }
            __syncthreads();
        }
        int chosen = ri[0];
        if (tid == 0) {
            top[bh * NTOP_ + u] = chosen;
            sel[(size_t)bh * L_ + chosen] = u + 1;
            vals[chosen] = -INFINITY;
        }
        __syncthreads();
    }
}

// ---------------- full attention for each selected row ------------------
__global__ void attn_kernel(const float* __restrict__ q, const float* __restrict__ k,
                            const float* __restrict__ v, const float* __restrict__ pad,
                            const int* __restrict__ top, float* __restrict__ upd) {
    int u = blockIdx.x, bh = blockIdx.y;
    int b = bh >> 3, h = bh & 7;
    __shared__ float sc[L_];
    __shared__ float qs[DH_];
    __shared__ float red[8];
    __shared__ float bc[2];
    __shared__ float updp[4][DH_];
    int tid = threadIdx.x; // 256
    int w = tid >> 5, lane = tid & 31;

    int qi = top[bh * NTOP_ + u];
    float pd = pad[b * L_ + qi];
    if (tid < DH_) qs[tid] = q[((size_t)b * L_ + qi) * DM_ + h * DH_ + tid];
    __syncthreads();

    const float scale = 0.044194173824159216f; // 1/sqrt(512)
    for (int kk = tid; kk < L_; kk += 256) {
        const float4* kr = reinterpret_cast<const float4*>(
            &k[((size_t)b * L_ + kk) * DM_ + h * DH_]);
        float s0 = 0.f, s1 = 0.f, s2 = 0.f, s3 = 0.f;
        #pragma unroll
        for (int d = 0; d < DH_ / 4; d++) {
            float4 kv = kr[d];
            s0 += qs[d * 4 + 0] * kv.x;
            s1 += qs[d * 4 + 1] * kv.y;
            s2 += qs[d * 4 + 2] * kv.z;
            s3 += qs[d * 4 + 3] * kv.w;
        }
        float s = ((s0 + s1) + (s2 + s3)) * scale;
        bool m = (kk <= qi) && (pd != 0.f);
        sc[kk] = m ? s : -100000.0f;
    }
    __syncthreads();

    float mx = -INFINITY;
    for (int kk = tid; kk < L_; kk += 256) mx = fmaxf(mx, sc[kk]);
    #pragma unroll
    for (int o = 16; o; o >>= 1) mx = fmaxf(mx, __shfl_xor_sync(0xffffffffu, mx, o));
    if (lane == 0) red[w] = mx;
    __syncthreads();
    if (tid == 0) {
        float m2 = red[0];
        #pragma unroll
        for (int i = 1; i < 8; i++) m2 = fmaxf(m2, red[i]);
        bc[0] = m2;
    }
    __syncthreads();
    float Mx = bc[0];

    float ls = 0.f;
    for (int kk = tid; kk < L_; kk += 256) {
        float e = __expf(sc[kk] - Mx);
        sc[kk] = e;
        ls += e;
    }
    #pragma unroll
    for (int o = 16; o; o >>= 1) ls += __shfl_xor_sync(0xffffffffu, ls, o);
    if (lane == 0) red[w] = ls;
    __syncthreads();
    if (tid == 0) {
        float s2 = 0.f;
        #pragma unroll
        for (int i = 0; i < 8; i++) s2 += red[i];
        bc[1] = s2;
    }
    __syncthreads();
    float invS = 1.0f / bc[1];

    int d = tid & 63, g = tid >> 6;
    float acc = 0.f;
    for (int kk = g; kk < L_; kk += 4)
        acc += sc[kk] * v[((size_t)b * L_ + kk) * DM_ + h * DH_ + d];
    updp[g][d] = acc;
    __syncthreads();
    if (tid < DH_) {
        float r = (updp[0][tid] + updp[1][tid] + updp[2][tid] + updp[3][tid]) * invS;
        upd[((size_t)bh * NTOP_ + u) * DH_ + tid] = r;
    }
}

// ---------------- padding cumsum per batch: parallel block scan ----------
// 256 threads; each scans 8 consecutive elems locally, Hillis-Steele over totals.
__global__ void padc_kernel(const float* __restrict__ pad, float* __restrict__ padc) {
    int b = blockIdx.x;
    int tid = threadIdx.x; // 256
    __shared__ float bs[256];

    float x[8];
    float s = 0.f;
    #pragma unroll
    for (int j = 0; j < 8; j++) {
        x[j] = pad[b * L_ + tid * 8 + j];
        s += x[j];
    }
    bs[tid] = s;
    __syncthreads();
    // inclusive Hillis-Steele over 256 thread totals
    for (int off = 1; off < 256; off <<= 1) {
        float t = (tid >= off) ? bs[tid - off] : 0.f;
        __syncthreads();
        bs[tid] += t;
        __syncthreads();
    }
    float run = bs[tid] - s;  // exclusive prefix
    #pragma unroll
    for (int j = 0; j < 8; j++) {
        run += x[j];
        padc[b * L_ + tid * 8 + j] = run;
    }
}

// ---------------- v_avg cumsum + scatter selected rows -------------------
// grid (H, B), 512 threads: 8 L-chunks x 64 dims, two-phase chunked prefix.
__global__ void assemble_kernel(const float* __restrict__ v, const float* __restrict__ padc,
                                const int* __restrict__ sel, const float* __restrict__ upd,
                                float* __restrict__ out1) {
    int h = blockIdx.x, b = blockIdx.y;
    int tid = threadIdx.x;       // 512
    int c = tid >> 6;            // chunk 0..7
    int d = tid & 63;
    const int CH = L_ / 8;       // 256
    __shared__ float pref[8][DH_];
    int bh = b * H_ + h;

    // phase 1: per-chunk sums
    float s = 0.f;
    for (int i = c * CH; i < (c + 1) * CH; i++)
        s += v[((size_t)b * L_ + i) * DM_ + h * DH_ + d];
    pref[c][d] = s;
    __syncthreads();

    // exclusive prefix over chunks (one thread per d)
    if (tid < DH_) {
        float run = 0.f;
        #pragma unroll
        for (int cc = 0; cc < 8; cc++) {
            float t = pref[cc][tid];
            pref[cc][tid] = run;
            run += t;
        }
    }
    __syncthreads();

    // phase 2: walk chunk with carried prefix
    float acc = pref[c][d];
    for (int i = c * CH; i < (c + 1) * CH; i++) {
        acc += v[((size_t)b * L_ + i) * DM_ + h * DH_ + d];
        int sv = sel[(size_t)bh * L_ + i];
        float val;
        if (sv > 0)
            val = upd[((size_t)bh * NTOP_ + (sv - 1)) * DH_ + d];
        else
            val = acc / (padc[b * L_ + i] + 1e-12f);
        out1[((size_t)b * L_ + i) * DM_ + h * DH_ + d] = val;
    }
}

// ---------------- launch ------------------------------------------------
extern "C" void kernel_launch(void* const* d_in, const int* in_sizes, int n_in,
                              void* d_out, int out_size) {
    (void)in_sizes; (void)n_in; (void)out_size;
    const float* queries = (const float*)d_in[0];
    const float* keys    = (const float*)d_in[1];
    const float* values  = (const float*)d_in[2];
    const float* pad     = (const float*)d_in[3];
    const float* Wq      = (const float*)d_in[4];
    const float* bq      = (const float*)d_in[5];
    const float* Wk      = (const float*)d_in[6];
    const float* bk      = (const float*)d_in[7];
    const float* Wv      = (const float*)d_in[8];
    const float* bv      = (const float*)d_in[9];
    const float* Wf      = (const float*)d_in[10];
    const float* bf      = (const float*)d_in[11];
    const float* qln_w   = (const float*)d_in[12];
    const float* qln_b   = (const float*)d_in[13];
    const float* fln_w   = (const float*)d_in[14];
    const float* fln_b   = (const float*)d_in[15];
    const int*   idx     = (const int*)d_in[16];
    float* out = (float*)d_out;

    float *p_lnq, *p_q, *p_k, *p_v, *p_out1, *p_out2, *p_M, *p_upd, *p_padc;
    int *p_top, *p_sel;
    cudaGetSymbolAddress((void**)&p_lnq,  g_lnq);
    cudaGetSymbolAddress((void**)&p_q,    g_q);
    cudaGetSymbolAddress((void**)&p_k,    g_k);
    cudaGetSymbolAddress((void**)&p_v,    g_v);
    cudaGetSymbolAddress((void**)&p_out1, g_out1);
    cudaGetSymbolAddress((void**)&p_out2, g_out2);
    cudaGetSymbolAddress((void**)&p_M,    g_M);
    cudaGetSymbolAddress((void**)&p_upd,  g_upd);
    cudaGetSymbolAddress((void**)&p_padc, g_padc);
    cudaGetSymbolAddress((void**)&p_top,  g_top);
    cudaGetSymbolAddress((void**)&p_sel,  g_sel);

    const int smem_ss = (SK_ * DM_ + DM_) * sizeof(float); // 51200
    cudaFuncSetAttribute(sample_score_kernel,
                         cudaFuncAttributeMaxDynamicSharedMemorySize, smem_ss);

    int rowsBL = B_ * L_;

    // 1. LN on queries
    ln_kernel<<<rowsBL, 256>>>(queries, qln_w, qln_b, p_lnq);

    // 2. fused q/k/v projections
    Gemm3Args ga3;
    ga3.A[0] = p_lnq; ga3.A[1] = keys; ga3.A[2] = values;
    ga3.W[0] = Wq;    ga3.W[1] = Wk;   ga3.W[2] = Wv;
    ga3.bias[0] = bq; ga3.bias[1] = bk; ga3.bias[2] = bv;
    ga3.C[0] = p_q;   ga3.C[1] = p_k;  ga3.C[2] = p_v;
    dim3 gg3(DM_ / 128, rowsBL / 128, 3);
    gemm_bias3<<<gg3, 256>>>(ga3);

    // 3. sampled score statistic M
    dim3 gs(L_, B_);
    sample_score_kernel<<<gs, 256, smem_ss>>>(p_q, p_k, idx, p_M);

    // 4. top-24 per (b,h) + selection map
    topk_kernel<<<B_ * H_, 256>>>(p_M, p_top, p_sel);

    // 5. full attention on selected rows
    dim3 ga(NTOP_, B_ * H_);
    attn_kernel<<<ga, 256>>>(p_q, p_k, p_v, pad, p_top, p_upd);

    // 6. padding cumsum (parallel scan)
    padc_kernel<<<B_, 256>>>(pad, p_padc);

    // 7. assemble v_avg + scatter (chunked parallel prefix)
    dim3 gasm(H_, B_);
    assemble_kernel<<<gasm, 512>>>(p_v, p_padc, p_sel, p_upd, p_out1);

    // 8. output projection
    dim3 gg(DM_ / 128, rowsBL / 128);
    gemm_bias<<<gg, 256>>>(p_out1, Wf, bf, p_out2);

    // 9. final LN
    ln_kernel<<<rowsBL, 256>>>(p_out2, fln_w, fln_b, out);
}

// round 16
// speedup vs baseline: 1.8272x; 1.0168x over previous
#include <cuda_runtime.h>
#include <cuda_bf16.h>
#include <mma.h>
#include <math.h>

using namespace nvcuda;

#define B_   8
#define L_   2048
#define DM_  512
#define H_   8
#define DH_  64
#define SK_  24
#define NTOP_ 24

// ---------------- device scratch (no cudaMalloc allowed) ----------------
__device__ float g_lnq [B_ * L_ * DM_];
__device__ float g_q   [B_ * L_ * DM_];
__device__ float g_k   [B_ * L_ * DM_];
__device__ float g_v   [B_ * L_ * DM_];
__device__ float g_out1[B_ * L_ * DM_];
__device__ float g_out2[B_ * L_ * DM_];
__device__ float g_M   [B_ * H_ * L_];
__device__ int   g_top [B_ * H_ * NTOP_];
__device__ int   g_sel [B_ * H_ * L_];
__device__ float g_upd [B_ * H_ * NTOP_ * DH_];
__device__ float g_padc[B_ * L_];

// ---------------- LayerNorm over last dim (512), one block per row ------
__global__ void ln_kernel(const float* __restrict__ x, const float* __restrict__ w,
                          const float* __restrict__ bb, float* __restrict__ out) {
    int row = blockIdx.x;
    int tid = threadIdx.x; // 256 threads, 2 elems each
    const float2* xr = reinterpret_cast<const float2*>(x + (size_t)row * DM_);
    float2 v = xr[tid];
    __shared__ float red[8];

    float s = v.x + v.y;
    #pragma unroll
    for (int o = 16; o; o >>= 1) s += __shfl_xor_sync(0xffffffffu, s, o);
    if ((tid & 31) == 0) red[tid >> 5] = s;
    __syncthreads();
    float tot = 0.f;
    #pragma unroll
    for (int i = 0; i < 8; i++) tot += red[i];
    float mean = tot * (1.f / DM_);

    float d0 = v.x - mean, d1 = v.y - mean;
    float sq = d0 * d0 + d1 * d1;
    __syncthreads();
    #pragma unroll
    for (int o = 16; o; o >>= 1) sq += __shfl_xor_sync(0xffffffffu, sq, o);
    if ((tid & 31) == 0) red[tid >> 5] = sq;
    __syncthreads();
    float vtot = 0.f;
    #pragma unroll
    for (int i = 0; i < 8; i++) vtot += red[i];
    float inv = rsqrtf(vtot * (1.f / DM_) + 1e-8f);

    float2 wv = reinterpret_cast<const float2*>(w)[tid];
    float2 bv = reinterpret_cast<const float2*>(bb)[tid];
    float2 o;
    o.x = wv.x * d0 * inv + bv.x;
    o.y = wv.y * d1 * inv + bv.y;
    reinterpret_cast<float2*>(out + (size_t)row * DM_)[tid] = o;
}

// ---------------- fp32 GEMM body (used for q/k projections: top-k safe) -
__device__ __forceinline__ void gemm_body(const float* __restrict__ A,
                                          const float* __restrict__ W,
                                          const float* __restrict__ bias,
                                          float* __restrict__ C,
                                          int bm, int bn) {
    const int K = 512, N = 512;
    __shared__ float As[8][128 + 4];
    __shared__ float Bs[8][128 + 4];
    int tid = threadIdx.x;

    int arow = tid >> 1;
    int acol = (tid & 1) * 4;
    int brow = tid >> 5;
    int bcol = (tid & 31) * 4;
    int tx = tid & 15, ty = tid >> 4;

    float acc[8][8];
    #pragma unroll
    for (int i = 0; i < 8; i++)
        #pragma unroll
        for (int j = 0; j < 8; j++) acc[i][j] = 0.f;

    float4 av = *reinterpret_cast<const float4*>(&A[(size_t)(bm + arow) * K + acol]);
    float4 bv = *reinterpret_cast<const float4*>(&W[(size_t)brow * N + bn + bcol]);

    for (int k0 = 0; k0 < K; k0 += 8) {
        As[acol + 0][arow] = av.x;
        As[acol + 1][arow] = av.y;
        As[acol + 2][arow] = av.z;
        As[acol + 3][arow] = av.w;
        Bs[brow][bcol + 0] = bv.x;
        Bs[brow][bcol + 1] = bv.y;
        Bs[brow][bcol + 2] = bv.z;
        Bs[brow][bcol + 3] = bv.w;
        __syncthreads();

        if (k0 + 8 < K) {
            av = *reinterpret_cast<const float4*>(&A[(size_t)(bm + arow) * K + k0 + 8 + acol]);
            bv = *reinterpret_cast<const float4*>(&W[(size_t)(k0 + 8 + brow) * N + bn + bcol]);
        }

        #pragma unroll
        for (int kk = 0; kk < 8; kk++) {
            float4 a0 = *reinterpret_cast<const float4*>(&As[kk][ty * 8]);
            float4 a1 = *reinterpret_cast<const float4*>(&As[kk][ty * 8 + 4]);
            float4 b0 = *reinterpret_cast<const float4*>(&Bs[kk][tx * 8]);
            float4 b1 = *reinterpret_cast<const float4*>(&Bs[kk][tx * 8 + 4]);
            float a[8] = {a0.x, a0.y, a0.z, a0.w, a1.x, a1.y, a1.z, a1.w};
            float b[8] = {b0.x, b0.y, b0.z, b0.w, b1.x, b1.y, b1.z, b1.w};
            #pragma unroll
            for (int i = 0; i < 8; i++)
                #pragma unroll
                for (int j = 0; j < 8; j++) acc[i][j] += a[i] * b[j];
        }
        __syncthreads();
    }

    #pragma unroll
    for (int i = 0; i < 8; i++) {
        int row = bm + ty * 8 + i;
        #pragma unroll
        for (int j = 0; j < 8; j += 4) {
            int col = bn + tx * 8 + j;
            float4 o;
            o.x = acc[i][j + 0] + bias[col + 0];
            o.y = acc[i][j + 1] + bias[col + 1];
            o.z = acc[i][j + 2] + bias[col + 2];
            o.w = acc[i][j + 3] + bias[col + 3];
            *reinterpret_cast<float4*>(&C[(size_t)row * N + col]) = o;
        }
    }
}

// fused q/k projection: blockIdx.z selects which GEMM
struct Gemm3Args {
    const float* A[3];
    const float* W[3];
    const float* bias[3];
    float* C[3];
};

__global__ void __launch_bounds__(256, 2) gemm_bias3(Gemm3Args args) {
    int z = blockIdx.z;
    gemm_body(args.A[z], args.W[z], args.bias[z], args.C[z],
              blockIdx.y * 128, blockIdx.x * 128);
}

// ---------------- tf32 WMMA GEMM (used for v / output projections) ------
// C[M,512] = A[M,512] @ W[512,512] + bias. Block 128x128, 8 warps (2x4),
// warp tile 64x32 = 4x2 wmma m16n16k8 tiles, K-tile 32.
// NOTE: all load/store_matrix_sync ldm values are multiples of 4 elements
// (16B) and all fragment base pointers are 32B-aligned, per the WMMA spec
// (ldm=17 in the R13 revision was UB and produced garbage).
#define KT_ 32
__global__ void __launch_bounds__(256, 2) gemm_bias_tf32(const float* __restrict__ A,
                                                         const float* __restrict__ W,
                                                         const float* __restrict__ bias,
                                                         float* __restrict__ C) {
    const int K = 512, N = 512;
    __shared__ __align__(32) float As[128][KT_ + 8];  // stride 40 fl = 160B (32B mult)
    __shared__ __align__(32) float Ws[KT_][128 + 8];  // stride 136 fl = 544B (32B mult)
    int tid = threadIdx.x;
    int wid = tid >> 5, lane = tid & 31;
    int bm = blockIdx.y * 128, bn = blockIdx.x * 128;
    int wm = (wid >> 2) * 64;              // warp row offset: 0 or 64
    int wn = (wid & 3) * 32;               // warp col offset: 0,32,64,96

    wmma::fragment<wmma::accumulator, 16, 16, 8, float> acc[4][2];
    #pragma unroll
    for (int i = 0; i < 4; i++)
        #pragma unroll
        for (int j = 0; j < 2; j++) wmma::fill_fragment(acc[i][j], 0.0f);

    for (int k0 = 0; k0 < K; k0 += KT_) {
        // load A tile 128x32: thread t -> row t/2, cols (t&1)*16 .. +15
        {
            int row = tid >> 1, c0 = (tid & 1) * 16;
            const float4* src = reinterpret_cast<const float4*>(&A[(size_t)(bm + row) * K + k0 + c0]);
            float4 v0 = src[0], v1 = src[1], v2 = src[2], v3 = src[3];
            *reinterpret_cast<float4*>(&As[row][c0 + 0])  = v0;
            *reinterpret_cast<float4*>(&As[row][c0 + 4])  = v1;
            *reinterpret_cast<float4*>(&As[row][c0 + 8])  = v2;
            *reinterpret_cast<float4*>(&As[row][c0 + 12]) = v3;
        }
        // load W tile 32x128: thread t -> row t/8, cols (t&7)*16 .. +15
        {
            int row = tid >> 3, c0 = (tid & 7) * 16;
            const float4* src = reinterpret_cast<const float4*>(&W[(size_t)(k0 + row) * N + bn + c0]);
            float4 v0 = src[0], v1 = src[1], v2 = src[2], v3 = src[3];
            *reinterpret_cast<float4*>(&Ws[row][c0 + 0])  = v0;
            *reinterpret_cast<float4*>(&Ws[row][c0 + 4])  = v1;
            *reinterpret_cast<float4*>(&Ws[row][c0 + 8])  = v2;
            *reinterpret_cast<float4*>(&Ws[row][c0 + 12]) = v3;
        }
        __syncthreads();

        #pragma unroll
        for (int kk = 0; kk < KT_; kk += 8) {
            wmma::fragment<wmma::matrix_a, 16, 16, 8, wmma::precision::tf32, wmma::row_major> af[4];
            wmma::fragment<wmma::matrix_b, 16, 16, 8, wmma::precision::tf32, wmma::row_major> bf[2];
            #pragma unroll
            for (int i = 0; i < 4; i++) {
                wmma::load_matrix_sync(af[i], &As[wm + i * 16][kk], KT_ + 8);
                #pragma unroll
                for (int t = 0; t < af[i].num_elements; t++)
                    af[i].x[t] = wmma::__float_to_tf32(af[i].x[t]);
            }
            #pragma unroll
            for (int j = 0; j < 2; j++) {
                wmma::load_matrix_sync(bf[j], &Ws[kk][wn + j * 16], 128 + 8);
                #pragma unroll
                for (int t = 0; t < bf[j].num_elements; t++)
                    bf[j].x[t] = wmma::__float_to_tf32(bf[j].x[t]);
            }
            #pragma unroll
            for (int i = 0; i < 4; i++)
                #pragma unroll
                for (int j = 0; j < 2; j++)
                    wmma::mma_sync(acc[i][j], af[i], bf[j], acc[i][j]);
        }
        __syncthreads();
    }

    // epilogue: per-warp smem roundtrip (reuse As region), add bias, store.
    // stage ldm = 24 floats (96B, multiple of 32B); per-warp offset 384 floats
    // (1536B, 32B-aligned); 8 warps * 384 = 3072 <= 5120 floats available.
    float* stage = &As[0][0] + wid * 384;
    #pragma unroll
    for (int i = 0; i < 4; i++) {
        #pragma unroll
        for (int j = 0; j < 2; j++) {
            wmma::store_matrix_sync(stage, acc[i][j], 24, wmma::mem_row_major);
            __syncwarp();
            int r = lane >> 1, c0 = (lane & 1) * 8;
            int grow = bm + wm + i * 16 + r;
            int gcol = bn + wn + j * 16 + c0;
            #pragma unroll
            for (int c = 0; c < 8; c++)
                C[(size_t)grow * N + gcol + c] = stage[r * 24 + c0 + c] + bias[gcol + c];
            __syncwarp();
        }
    }
}

// ---------------- sampled scores: M[b,h,i] = max_j(q.ks_j) - sum_j/L ----
__global__ void sample_score_kernel(const float* __restrict__ q, const float* __restrict__ k,
                                    const int* __restrict__ idx, float* __restrict__ Mout) {
    int i = blockIdx.x, b = blockIdx.y;
    extern __shared__ float sh[];            // ks[24][512] then q[512]
    float* ks = sh;
    float* qs = sh + SK_ * DM_;
    __shared__ int sidx[SK_];
    int tid = threadIdx.x; // 256

    if (tid < SK_) sidx[tid] = idx[i * SK_ + tid];
    __syncthreads();

    const float4* qrow = reinterpret_cast<const float4*>(q + ((size_t)b * L_ + i) * DM_);
    for (int t = tid; t < DM_ / 4; t += 256)
        reinterpret_cast<float4*>(qs)[t] = qrow[t];
    for (int t = tid; t < SK_ * (DM_ / 4); t += 256) {
        int j = t >> 7, c = t & 127;
        reinterpret_cast<float4*>(ks + j * DM_)[c] =
            reinterpret_cast<const float4*>(k + ((size_t)b * L_ + sidx[j]) * DM_)[c];
    }
    __syncthreads();

    int w = tid >> 5, lane = tid & 31;
    int h = w;
    float mx = -INFINITY, sm = 0.f;
    #pragma unroll 4
    for (int j = 0; j < SK_; j++) {
        float p = qs[h * DH_ + lane]      * ks[j * DM_ + h * DH_ + lane]
                + qs[h * DH_ + 32 + lane] * ks[j * DM_ + h * DH_ + 32 + lane];
        #pragma unroll
        for (int o = 16; o; o >>= 1) p += __shfl_xor_sync(0xffffffffu, p, o);
        mx = fmaxf(mx, p);
        sm += p;
    }
    if (lane == 0)
        Mout[((size_t)(b * H_ + h)) * L_ + i] = mx - sm * (1.0f / (float)L_);
}

// ---------------- top-24 per (b,h), iterative argmax; also build sel map -
__global__ void topk_kernel(const float* __restrict__ M, int* __restrict__ top,
                            int* __restrict__ sel) {
    int bh = blockIdx.x;
    __shared__ float vals[L_];
    __shared__ float rv[256];
    __shared__ int   ri[256];
    int tid = threadIdx.x; // 256

    for (int t = tid; t < L_; t += 256) {
        vals[t] = M[(size_t)bh * L_ + t];
        sel[(size_t)bh * L_ + t] = 0;
    }
    __syncthreads();

    for (int u = 0; u < NTOP_; u++) {
        float best = -INFINITY; int bi = L_;
        for (int t = tid; t < L_; t += 256) {
            float v = vals[t];
            if (v > best) { best = v; bi = t; }
        }
        rv[tid] = best; ri[tid] = bi;
        __syncthreads();
        for (int s = 128; s > 0; s >>= 1) {
            if (tid < s) {
                float ov = rv[tid + s]; int oi = ri[tid + s];
                if (ov > rv[tid] || (ov == rv[tid] && oi < ri[tid])) {
                    rv[tid] = ov; ri[tid] = oi;
                }
            }
            __syncthreads();
        }
        int chosen = ri[0];
        if (tid == 0) {
            top[bh * NTOP_ + u] = chosen;
            sel[(size_t)bh * L_ + chosen] = u + 1;
            vals[chosen] = -INFINITY;
        }
        __syncthreads();
    }
}

// ---------------- full attention for each selected row ------------------
__global__ void attn_kernel(const float* __restrict__ q, const float* __restrict__ k,
                            const float* __restrict__ v, const float* __restrict__ pad,
                            const int* __restrict__ top, float* __restrict__ upd) {
    int u = blockIdx.x, bh = blockIdx.y;
    int b = bh >> 3, h = bh & 7;
    __shared__ float sc[L_];
    __shared__ float qs[DH_];
    __shared__ float red[8];
    __shared__ float bc[2];
    __shared__ float updp[4][DH_];
    int tid = threadIdx.x; // 256
    int w = tid >> 5, lane = tid & 31;

    int qi = top[bh * NTOP_ + u];
    float pd = pad[b * L_ + qi];
    if (tid < DH_) qs[tid] = q[((size_t)b * L_ + qi) * DM_ + h * DH_ + tid];
    __syncthreads();

    const float scale = 0.044194173824159216f; // 1/sqrt(512)
    for (int kk = tid; kk < L_; kk += 256) {
        const float4* kr = reinterpret_cast<const float4*>(
            &k[((size_t)b * L_ + kk) * DM_ + h * DH_]);
        float s0 = 0.f, s1 = 0.f, s2 = 0.f, s3 = 0.f;
        #pragma unroll
        for (int d = 0; d < DH_ / 4; d++) {
            float4 kv = kr[d];
            s0 += qs[d * 4 + 0] * kv.x;
            s1 += qs[d * 4 + 1] * kv.y;
            s2 += qs[d * 4 + 2] * kv.z;
            s3 += qs[d * 4 + 3] * kv.w;
        }
        float s = ((s0 + s1) + (s2 + s3)) * scale;
        bool m = (kk <= qi) && (pd != 0.f);
        sc[kk] = m ? s : -100000.0f;
    }
    __syncthreads();

    float mx = -INFINITY;
    for (int kk = tid; kk < L_; kk += 256) mx = fmaxf(mx, sc[kk]);
    #pragma unroll
    for (int o = 16; o; o >>= 1) mx = fmaxf(mx, __shfl_xor_sync(0xffffffffu, mx, o));
    if (lane == 0) red[w] = mx;
    __syncthreads();
    if (tid == 0) {
        float m2 = red[0];
        #pragma unroll
        for (int i = 1; i < 8; i++) m2 = fmaxf(m2, red[i]);
        bc[0] = m2;
    }
    __syncthreads();
    float Mx = bc[0];

    float ls = 0.f;
    for (int kk = tid; kk < L_; kk += 256) {
        float e = __expf(sc[kk] - Mx);
        sc[kk] = e;
        ls += e;
    }
    #pragma unroll
    for (int o = 16; o; o >>= 1) ls += __shfl_xor_sync(0xffffffffu, ls, o);
    if (lane == 0) red[w] = ls;
    __syncthreads();
    if (tid == 0) {
        float s2 = 0.f;
        #pragma unroll
        for (int i = 0; i < 8; i++) s2 += red[i];
        bc[1] = s2;
    }
    __syncthreads();
    float invS = 1.0f / bc[1];

    int d = tid & 63, g = tid >> 6;
    float acc = 0.f;
    for (int kk = g; kk < L_; kk += 4)
        acc += sc[kk] * v[((size_t)b * L_ + kk) * DM_ + h * DH_ + d];
    updp[g][d] = acc;
    __syncthreads();
    if (tid < DH_) {
        float r = (updp[0][tid] + updp[1][tid] + updp[2][tid] + updp[3][tid]) * invS;
        upd[((size_t)bh * NTOP_ + u) * DH_ + tid] = r;
    }
}

// ---------------- padding cumsum per batch: parallel block scan ----------
__global__ void padc_kernel(const float* __restrict__ pad, float* __restrict__ padc) {
    int b = blockIdx.x;
    int tid = threadIdx.x; // 256
    __shared__ float bs[256];

    float x[8];
    float s = 0.f;
    #pragma unroll
    for (int j = 0; j < 8; j++) {
        x[j] = pad[b * L_ + tid * 8 + j];
        s += x[j];
    }
    bs[tid] = s;
    __syncthreads();
    for (int off = 1; off < 256; off <<= 1) {
        float t = (tid >= off) ? bs[tid - off] : 0.f;
        __syncthreads();
        bs[tid] += t;
        __syncthreads();
    }
    float run = bs[tid] - s;  // exclusive prefix
    #pragma unroll
    for (int j = 0; j < 8; j++) {
        run += x[j];
        padc[b * L_ + tid * 8 + j] = run;
    }
}

// ---------------- v_avg cumsum + scatter selected rows -------------------
__global__ void assemble_kernel(const float* __restrict__ v, const float* __restrict__ padc,
                                const int* __restrict__ sel, const float* __restrict__ upd,
                                float* __restrict__ out1) {
    int h = blockIdx.x, b = blockIdx.y;
    int tid = threadIdx.x;       // 512
    int c = tid >> 6;            // chunk 0..7
    int d = tid & 63;
    const int CH = L_ / 8;       // 256
    __shared__ float pref[8][DH_];
    int bh = b * H_ + h;

    float s = 0.f;
    for (int i = c * CH; i < (c + 1) * CH; i++)
        s += v[((size_t)b * L_ + i) * DM_ + h * DH_ + d];
    pref[c][d] = s;
    __syncthreads();

    if (tid < DH_) {
        float run = 0.f;
        #pragma unroll
        for (int cc = 0; cc < 8; cc++) {
            float t = pref[cc][tid];
            pref[cc][tid] = run;
            run += t;
        }
    }
    __syncthreads();

    float acc = pref[c][d];
    for (int i = c * CH; i < (c + 1) * CH; i++) {
        acc += v[((size_t)b * L_ + i) * DM_ + h * DH_ + d];
        int sv = sel[(size_t)bh * L_ + i];
        float val;
        if (sv > 0)
            val = upd[((size_t)bh * NTOP_ + (sv - 1)) * DH_ + d];
        else
            val = acc / (padc[b * L_ + i] + 1e-12f);
        out1[((size_t)b * L_ + i) * DM_ + h * DH_ + d] = val;
    }
}

// ---------------- launch ------------------------------------------------
extern "C" void kernel_launch(void* const* d_in, const int* in_sizes, int n_in,
                              void* d_out, int out_size) {
    (void)in_sizes; (void)n_in; (void)out_size;
    const float* queries = (const float*)d_in[0];
    const float* keys    = (const float*)d_in[1];
    const float* values  = (const float*)d_in[2];
    const float* pad     = (const float*)d_in[3];
    const float* Wq      = (const float*)d_in[4];
    const float* bq      = (const float*)d_in[5];
    const float* Wk      = (const float*)d_in[6];
    const float* bk      = (const float*)d_in[7];
    const float* Wv      = (const float*)d_in[8];
    const float* bv      = (const float*)d_in[9];
    const float* Wf      = (const float*)d_in[10];
    const float* bf      = (const float*)d_in[11];
    const float* qln_w   = (const float*)d_in[12];
    const float* qln_b   = (const float*)d_in[13];
    const float* fln_w   = (const float*)d_in[14];
    const float* fln_b   = (const float*)d_in[15];
    const int*   idx     = (const int*)d_in[16];
    float* out = (float*)d_out;

    float *p_lnq, *p_q, *p_k, *p_v, *p_out1, *p_out2, *p_M, *p_upd, *p_padc;
    int *p_top, *p_sel;
    cudaGetSymbolAddress((void**)&p_lnq,  g_lnq);
    cudaGetSymbolAddress((void**)&p_q,    g_q);
    cudaGetSymbolAddress((void**)&p_k,    g_k);
    cudaGetSymbolAddress((void**)&p_v,    g_v);
    cudaGetSymbolAddress((void**)&p_out1, g_out1);
    cudaGetSymbolAddress((void**)&p_out2, g_out2);
    cudaGetSymbolAddress((void**)&p_M,    g_M);
    cudaGetSymbolAddress((void**)&p_upd,  g_upd);
    cudaGetSymbolAddress((void**)&p_padc, g_padc);
    cudaGetSymbolAddress((void**)&p_top,  g_top);
    cudaGetSymbolAddress((void**)&p_sel,  g_sel);

    const int smem_ss = (SK_ * DM_ + DM_) * sizeof(float); // 51200
    cudaFuncSetAttribute(sample_score_kernel,
                         cudaFuncAttributeMaxDynamicSharedMemorySize, smem_ss);

    int rowsBL = B_ * L_;

    // 1. LN on queries
    ln_kernel<<<rowsBL, 256>>>(queries, qln_w, qln_b, p_lnq);

    // 2a. q/k projections (fp32 SIMT — protects discrete top-k)
    Gemm3Args ga3;
    ga3.A[0] = p_lnq; ga3.A[1] = keys; ga3.A[2] = keys;
    ga3.W[0] = Wq;    ga3.W[1] = Wk;   ga3.W[2] = Wk;
    ga3.bias[0] = bq; ga3.bias[1] = bk; ga3.bias[2] = bk;
    ga3.C[0] = p_q;   ga3.C[1] = p_k;  ga3.C[2] = p_k;
    dim3 gg2(DM_ / 128, rowsBL / 128, 2);
    gemm_bias3<<<gg2, 256>>>(ga3);

    // 2b. v projection (tf32 tensor cores — error flows only through smooth ops)
    dim3 ggt(DM_ / 128, rowsBL / 128);
    gemm_bias_tf32<<<ggt, 256>>>(values, Wv, bv, p_v);

    // 3. sampled score statistic M
    dim3 gs(L_, B_);
    sample_score_kernel<<<gs, 256, smem_ss>>>(p_q, p_k, idx, p_M);

    // 4. top-24 per (b,h) + selection map
    topk_kernel<<<B_ * H_, 256>>>(p_M, p_top, p_sel);

    // 5. full attention on selected rows
    dim3 ga(NTOP_, B_ * H_);
    attn_kernel<<<ga, 256>>>(p_q, p_k, p_v, pad, p_top, p_upd);

    // 6. padding cumsum (parallel scan)
    padc_kernel<<<B_, 256>>>(pad, p_padc);

    // 7. assemble v_avg + scatter (chunked parallel prefix)
    dim3 gasm(H_, B_);
    assemble_kernel<<<gasm, 512>>>(p_v, p_padc, p_sel, p_upd, p_out1);

    // 8. output projection (tf32 tensor cores)
    gemm_bias_tf32<<<ggt, 256>>>(p_out1, Wf, bf, p_out2);

    // 9. final LN
    ln_kernel<<<rowsBL, 256>>>(p_out2, fln_w, fln_b, out);
}